// round 9
// baseline (speedup 1.0000x reference)
#include <cuda_runtime.h>
#include <math_constants.h>

#define BATCH 262144
#define NLAYER 8
#define H 128
#define NSEG 129
#define BN_EPS 1e-5f
#define FLOW_EPS 1e-4f
#define INVALID 0xFFFFFFFFu
#define NREP 4
#define NB 148
#define NT 1024

// ---------------- device scratch (no allocs allowed) ----------------
__device__ unsigned g_arrive = 0, g_release = 0;   // grid barrier (monotonic, replay-safe)
__device__ double g_sum[2][2];                     // [parity][s,q]
__device__ int    g_cntR[2][NREP][NSEG];
__device__ float  g_s1R[2][NREP][NSEG], g_s2R[2][NREP][NSEG];
__device__ __align__(16) float g_tab[NSEG * H * 2];   // level-1 table (A,B per m,j)
__device__ float  g_kink2[NSEG * H];                  // sorted level-2 kinks per segment
__device__ __align__(16) float4 g_EF[NSEG * NSEG];    // (E0,F0,E1,F1) per (m, rank)
__device__ int    g_cursor[2][NSEG];
__device__ int    g_ptotal;
__device__ unsigned g_perm[BATCH + NSEG * 32];
__device__ float g_x[2 * BATCH];
__device__ float g_sldj[BATCH];

// grid-wide barrier: all NB blocks resident by construction
__device__ __forceinline__ void gridbar()
{
    __syncthreads();
    if (threadIdx.x == 0) {
        unsigned old = *(volatile unsigned*)&g_release;
        __threadfence();
        if (atomicAdd(&g_arrive, 1) == NB - 1) {
            atomicExch(&g_arrive, 0);
            __threadfence();
            atomicExch(&g_release, old + 1);
        } else {
            while (*(volatile unsigned*)&g_release == old) __nanosleep(32);
        }
        __threadfence();
    }
    __syncthreads();
}

// shared layout (float offsets)
#define XO_SA    0
#define XO_SC    128
#define XO_STHR  256
#define XO_STHS  384        // persists P1 -> P2 (scatter recomputes m)
#define XO_SORD  512
#define XO_SVR   640
#define XO_SCANA 768        // 132
#define XO_SCANB 904        // 132
#define XO_SCNT  1040       // int[129]; P2 reuses as float sN
#define XO_SS1   1172
#define XO_SS2   1304
#define XO_GHBH  1436       // 256
#define XO_C2    1692
#define XO_D2    1820
#define XO_TH2R  1948
#define XO_TH2S  2076
#define XO_ORD2  2204       // int[128]
#define XO_SCAN4 2332       // float4[130] (byte 9328, 16B aligned)
#define XO_RED4  2852       // float4[128] (byte 11408, 16B aligned)
#define XO_BCNT  3364       // int[129]
#define XO_BBASE 3496       // int[129]
#define XO_EOFF  3628       // int[130]
#define XO_MISC  3760
#define XO_KK2   3768       // float[129*128] level-2 kinks (P3)
#define X_FLOATS 20288
#define SMEM_ALL (X_FLOATS * 4)

__global__ void __launch_bounds__(NT, 1) k_all(
    const float* __restrict__ x,
    const float* __restrict__ v1,  const float* __restrict__ g1,  const float* __restrict__ b1,
    const float* __restrict__ bn1g,const float* __restrict__ bn1b,
    const float* __restrict__ v2,  const float* __restrict__ g2,  const float* __restrict__ b2,
    const float* __restrict__ bn2g,const float* __restrict__ bn2b,
    const float* __restrict__ wf,  const float* __restrict__ bf,
    float* __restrict__ out)
{
    extern __shared__ float X[];
    const int t = threadIdx.x, b = blockIdx.x;
    const int lane = t & 31, wid = t >> 5;

    // ================= P0: copy x, stats of x[:,1] into g_sum[0] =================
    {
        float kS = 0.f, cS = 0.f, kQ = 0.f, cQ = 0.f;
        for (int i = b * NT + t; i < BATCH; i += NB * NT) {
            float2 p = ((const float2*)x)[i];
            __stcg(((float2*)g_x) + i, p);
            float v = p.y;
            { float yk = v - cS; float tk = kS + yk; cS = (tk - kS) - yk; kS = tk; }
            float v2s = v * v;
            { float yk = v2s - cQ; float tk = kQ + yk; cQ = (tk - kQ) - yk; kQ = tk; }
        }
        double s = (double)kS, q = (double)kQ;
        for (int off = 16; off; off >>= 1) {
            s += __shfl_down_sync(0xffffffffu, s, off);
            q += __shfl_down_sync(0xffffffffu, q, off);
        }
        __shared__ double ss[32], sq[32];
        if (!lane) { ss[wid] = s; sq[wid] = q; }
        __syncthreads();
        if (!wid) {
            s = (lane < NT / 32) ? ss[lane] : 0.0;
            q = (lane < NT / 32) ? sq[lane] : 0.0;
            for (int off = 16; off; off >>= 1) {
                s += __shfl_down_sync(0xffffffffu, s, off);
                q += __shfl_down_sync(0xffffffffu, q, off);
            }
            if (!lane) { atomicAdd(&g_sum[0][0], s); atomicAdd(&g_sum[0][1], q); }
        }
        if (b == 1) {   // parity-0 buffers zero at start of each replay
            for (int idx = t; idx < NREP * NSEG; idx += NT) {
                ((int*)g_cntR[0])[idx] = 0;
                ((float*)g_s1R[0])[idx] = 0.f;
                ((float*)g_s2R[0])[idx] = 0.f;
            }
            for (int idx = t; idx < NSEG; idx += NT) g_cursor[0][idx] = 0;
        }
    }
    gridbar();

    for (int l = 0; l < NLAYER; l++) {
        const int par = l & 1, nxt = par ^ 1;
        const int uIdx = (l & 1) ^ 1, oIdx = 1 - uIdx;
        const int isLast = (l == NLAYER - 1);

        float* sa = X + XO_SA; float* sc = X + XO_SC; float* sthr = X + XO_STHR;
        float* sths = X + XO_STHS; int* sord = (int*)(X + XO_SORD); float* svr = X + XO_SVR;
        float* scanA = X + XO_SCANA; float* scanB = X + XO_SCANB;
        int* scnt = (int*)(X + XO_SCNT); float* ss1 = X + XO_SS1; float* ss2 = X + XO_SS2;
        float* miscf = X + XO_MISC;

        // ================= P1: BN1 fold + lvl1 sort + lvl1 table + hist =================
        if (t < H) {
            double mu = __ldcg(&g_sum[par][0]) * (1.0 / BATCH);
            double qq = __ldcg(&g_sum[par][1]) * (1.0 / BATCH);
            double var = qq - mu * mu;
            float meanu = (float)mu;
            float varu = (float)(var < 0.0 ? 0.0 : var);
            float v  = v1[l * H + t];
            float w1 = g1[l * H + t] * (v / fabsf(v));
            float r  = rsqrtf(w1 * w1 * varu + BN_EPS);
            float a  = w1 * bn1g[l * H + t] * r;
            float c  = bn1b[l * H + t] - a * meanu;
            sa[t] = a; sc[t] = c;
            sthr[t] = (a != 0.f) ? (-c / a) : CUDART_INF_F;
        }
        __syncthreads();
        if (t < H) {
            float th = sthr[t];
            int rank = 0;
            for (int j2 = 0; j2 < H; j2++) {
                float tj = sthr[j2];
                rank += (tj < th) || (tj == th && j2 < t);
            }
            sths[rank] = th; sord[rank] = t;
        }
        if (b == NB - 1) {  // zero next-parity buffers + next g_sum + next cursors
            for (int idx = t; idx < NREP * NSEG; idx += NT) {
                ((int*)g_cntR[nxt])[idx] = 0;
                ((float*)g_s1R[nxt])[idx] = 0.f;
                ((float*)g_s2R[nxt])[idx] = 0.f;
            }
            for (int idx = t; idx < NSEG; idx += NT) g_cursor[nxt][idx] = 0;
            if (t == 0) { g_sum[nxt][0] = 0.0; g_sum[nxt][1] = 0.0; }
        }
        __syncthreads();

        if (b < H) {  // build level-1 column j=b (prefix scan over sorted kinks)
            const int j = b;
            if (t < H) svr[t] = v2[l * H * H + j * H + t];
            __syncthreads();
            if (t == 0) {
                float nrm = 0.f;
                for (int tt = 0; tt < H; tt++) nrm = fmaf(svr[tt], svr[tt], nrm);
                miscf[0] = g2[l * H + j] / sqrtf(nrm);
            }
            __syncthreads();
            float wsc = miscf[0];
            float* redA = (float*)(X + XO_RED4);
            float* redB = redA + 128;
            if (t < H) {
                float aa = sa[t], cc = sc[t], w = wsc * svr[t];
                redA[t] = (aa < 0.f) ? w * aa : 0.f;
                redB[t] = (aa < 0.f) ? w * cc : ((aa == 0.f && cc > 0.f) ? w * cc : 0.f);
            }
            if (t >= 1 && t <= H) {
                int kk = sord[t - 1];
                float aa = sa[kk], cc = sc[kk], w = wsc * svr[kk];
                float sgn = (aa > 0.f) ? 1.f : ((aa < 0.f) ? -1.f : 0.f);
                scanA[t] = sgn * w * aa;
                scanB[t] = sgn * w * cc;
            }
            if (t == 0) { scanA[0] = 0.f; scanB[0] = 0.f; }
            __syncthreads();
            if (t == 0) {
                float A0 = 0.f, B0 = b2[l * H + j];
                for (int tt = 0; tt < H; tt++) { A0 += redA[tt]; B0 += redB[tt]; }
                miscf[1] = A0; miscf[2] = B0;
            }
            for (int off = 1; off <= H; off <<= 1) {
                float aadd = 0.f, badd = 0.f;
                if (t >= off && t <= H) { aadd = scanA[t - off]; badd = scanB[t - off]; }
                __syncthreads();
                if (t >= off && t <= H) { scanA[t] += aadd; scanB[t] += badd; }
                __syncthreads();
            }
            if (t <= H) {
                float2 val = make_float2(miscf[1] + scanA[t], miscf[2] + scanB[t]);
                __stcg(((float2*)g_tab) + t * H + j, val);
            }
        }
        __syncthreads();

        // hist (no mseg store; scatter recomputes m)
        for (int i = t; i < NSEG; i += NT) { scnt[i] = 0; ss1[i] = 0.f; ss2[i] = 0.f; }
        __syncthreads();
        for (int i = b * NT + t; i < BATCH; i += NB * NT) {
            float2 p = __ldcg(((const float2*)g_x) + i);
            float u = uIdx ? p.y : p.x;
            int m = 0;
#pragma unroll
            for (int s = 64; s >= 1; s >>= 1) { int nm = m + s; if (sths[nm - 1] < u) m = nm; }
            if (sths[H - 1] < u) m = H;

            bool lo = (m == 0), hi = (m == H);
            float u2 = u * u;
            float s1l = lo ? u : 0.f, s2l = lo ? u2 : 0.f;
            float s1h = hi ? u : 0.f, s2h = hi ? u2 : 0.f;
#pragma unroll
            for (int off = 16; off; off >>= 1) {
                s1l += __shfl_xor_sync(0xffffffffu, s1l, off);
                s2l += __shfl_xor_sync(0xffffffffu, s2l, off);
                s1h += __shfl_xor_sync(0xffffffffu, s1h, off);
                s2h += __shfl_xor_sync(0xffffffffu, s2h, off);
            }
            unsigned blo = __ballot_sync(0xffffffffu, lo);
            unsigned bhi = __ballot_sync(0xffffffffu, hi);
            if (lane == 0) {
                if (blo) { atomicAdd(&scnt[0], (int)__popc(blo)); atomicAdd(&ss1[0], s1l); atomicAdd(&ss2[0], s2l); }
                if (bhi) { atomicAdd(&scnt[H], (int)__popc(bhi)); atomicAdd(&ss1[H], s1h); atomicAdd(&ss2[H], s2h); }
            }
            if (!lo && !hi) {
                atomicAdd(&scnt[m], 1);
                atomicAdd(&ss1[m], u);
                atomicAdd(&ss2[m], u2);
            }
        }
        __syncthreads();
        {
            int r = b & (NREP - 1);
            for (int i = t; i < NSEG; i += NT) {
                if (scnt[i]) {
                    atomicAdd(&g_cntR[par][r][i], scnt[i]);
                    atomicAdd(&g_s1R[par][r][i], ss1[i]);
                    atomicAdd(&g_s2R[par][r][i], ss2[i]);
                }
            }
        }
        gridbar();

        // ================= P2: offsets + scatter (b<128) + ghbh/lvl2 build (b<=128) ============
        if (b <= H) {
            int* ecnt = (int*)(X + XO_SCNT);    // reuse as int counts first
            int* eoff = (int*)(X + XO_EOFF);
            int* bcnt = (int*)(X + XO_BCNT);
            int* bbase = (int*)(X + XO_BBASE);

            if (t < NSEG) {
                int c = 0;
#pragma unroll
                for (int r = 0; r < NREP; r++) c += __ldcg(&g_cntR[par][r][t]);
                ecnt[t] = c;
            }
            for (int i = t; i < NSEG; i += NT) bcnt[i] = 0;
            __syncthreads();
            if (t == 0) {
                int run = 0;
                for (int s = 0; s < NSEG; s++) { eoff[s] = run; run += (ecnt[s] + 31) & ~31; }
                eoff[NSEG] = run;
                if (b == H) g_ptotal = run;
            }
            __syncthreads();

            // ---- scatter (blocks 0..127; 2048 samples each) ----
            int m0s = -1, m1s = -1, r0s = 0, r1s = 0;
            int i0 = 0, i1 = 0;
            if (b < H) {
                i0 = b * 2048 + t; i1 = i0 + 1024;
                float2 p0 = __ldcg(((const float2*)g_x) + i0);
                float2 p1 = __ldcg(((const float2*)g_x) + i1);
                float u0 = uIdx ? p0.y : p0.x;
                float u1 = uIdx ? p1.y : p1.x;
                int m0 = 0, m1 = 0;
#pragma unroll
                for (int s = 64; s >= 1; s >>= 1) {
                    if (sths[m0 + s - 1] < u0) m0 += s;
                    if (sths[m1 + s - 1] < u1) m1 += s;
                }
                if (sths[H - 1] < u0) m0 = H;
                if (sths[H - 1] < u1) m1 = H;
                m0s = m0; m1s = m1;
                r0s = atomicAdd(&bcnt[m0], 1);
                r1s = atomicAdd(&bcnt[m1], 1);
            }
            __syncthreads();
            if (b < H) {
                if (t < NSEG) bbase[t] = bcnt[t] ? atomicAdd(&g_cursor[par][t], bcnt[t]) : 0;
            }
            __syncthreads();
            if (b < H) {
                __stcg(&g_perm[eoff[m0s] + bbase[m0s] + r0s], ((unsigned)m0s << 18) | (unsigned)i0);
                __stcg(&g_perm[eoff[m1s] + bbase[m1s] + r1s], ((unsigned)m1s << 18) | (unsigned)i1);
            }
            // padding INVALID for row b
            for (int p = eoff[b] + ecnt[b] + t; p < eoff[b + 1]; p += NT)
                __stcg(&g_perm[p], INVALID);

            // ---- ghbh (redundant per block) + level-2 build for segment m=b ----
            const int m = b;
            float* sN  = X + XO_SCNT;   // reuse as float now (counts consumed)
            float* s1v = X + XO_SS1;
            float* s2v = X + XO_SS2;
            float* ghbhS = X + XO_GHBH;
            float* c2 = X + XO_C2; float* d2 = X + XO_D2;
            float* th2r = X + XO_TH2R; float* th2s = X + XO_TH2S;
            int* ord2 = (int*)(X + XO_ORD2);
            float4* scan4 = (float4*)(X + XO_SCAN4);
            float4* red4  = (float4*)(X + XO_RED4);
            __syncthreads();
            if (t < NSEG) {
                float a = 0.f, bb = 0.f;
#pragma unroll
                for (int r = 0; r < NREP; r++) {
                    a  += __ldcg(&g_s1R[par][r][t]);
                    bb += __ldcg(&g_s2R[par][r][t]);
                }
                float cN = (float)ecnt[t];
                s1v[t] = a; s2v[t] = bb;
                sN[t] = cN;               // overwrites ecnt (same slot) AFTER reading it
            }
            __syncthreads();
            if (t < H) {   // ghbh_j, Kahan fp32
                float a1 = 0.f, c1 = 0.f, a2 = 0.f, c2k = 0.f;
                for (int mm = 0; mm < NSEG; mm++) {
                    float2 ab = __ldcg(((const float2*)g_tab) + mm * H + t);
                    float N = sN[mm], S1 = s1v[mm], S2 = s2v[mm];
                    float t1 = ab.x * S1 + ab.y * N;
                    float t2 = ab.x * (ab.x * S2 + 2.f * ab.y * S1) + ab.y * ab.y * N;
                    { float yk = t1 - c1; float tk = a1 + yk; c1 = (tk - a1) - yk; a1 = tk; }
                    { float yk = t2 - c2k; float tk = a2 + yk; c2k = (tk - a2) - yk; a2 = tk; }
                }
                float mean = a1 * (1.f / BATCH);
                float var  = a2 * (1.f / BATCH) - mean * mean;
                if (var < 0.f) var = 0.f;
                float gh = bn2g[l * H + t] * rsqrtf(var + BN_EPS);
                float bh = bn2b[l * H + t] - gh * mean;
                ghbhS[2 * t] = gh; ghbhS[2 * t + 1] = bh;
            }
            __syncthreads();
            if (t < H) {
                float2 ab = __ldcg(((const float2*)g_tab) + m * H + t);
                float gh = ghbhS[2 * t], bh = ghbhS[2 * t + 1];
                float c = gh * ab.x;
                float d = fmaf(gh, ab.y, bh);
                c2[t] = c; d2[t] = d;
                th2r[t] = (c != 0.f) ? (-d / c) : CUDART_INF_F;
            }
            __syncthreads();
            if (t < H) {
                float th = th2r[t];
                int rank = 0;
                for (int j2 = 0; j2 < H; j2++) {
                    float tj = th2r[j2];
                    rank += (tj < th) || (tj == th && j2 < t);
                }
                th2s[rank] = th; ord2[rank] = t;
            }
            if (t < H) {
                float c = c2[t], d = d2[t];
                float w0 = wf[(l * 2 + 0) * H + t], w1 = wf[(l * 2 + 1) * H + t];
                bool act = (c < 0.f) || (c == 0.f && d > 0.f);
                float4 bt;
                bt.x = (c < 0.f) ? w0 * c : 0.f;
                bt.z = (c < 0.f) ? w1 * c : 0.f;
                bt.y = act ? w0 * d : 0.f;
                bt.w = act ? w1 * d : 0.f;
                red4[t] = bt;
            }
            __syncthreads();
            for (int off = 64; off; off >>= 1) {
                if (t < off) {
                    float4 a4 = red4[t], b4 = red4[t + off];
                    red4[t] = make_float4(a4.x + b4.x, a4.y + b4.y, a4.z + b4.z, a4.w + b4.w);
                }
                __syncthreads();
            }
            if (t >= 1 && t <= H) {
                int j = ord2[t - 1];
                float c = c2[j], d = d2[j];
                float w0 = wf[(l * 2 + 0) * H + j], w1 = wf[(l * 2 + 1) * H + j];
                float sgn = (c > 0.f) ? 1.f : ((c < 0.f) ? -1.f : 0.f);
                scan4[t] = make_float4(sgn * w0 * c, sgn * w0 * d, sgn * w1 * c, sgn * w1 * d);
            }
            if (t == 0) scan4[0] = make_float4(0.f, 0.f, 0.f, 0.f);
            __syncthreads();
            for (int off = 1; off <= H; off <<= 1) {
                float4 add = make_float4(0.f, 0.f, 0.f, 0.f);
                if (t >= off && t <= H) add = scan4[t - off];
                __syncthreads();
                if (t >= off && t <= H) {
                    float4 s4 = scan4[t];
                    scan4[t] = make_float4(s4.x + add.x, s4.y + add.y, s4.z + add.z, s4.w + add.w);
                }
                __syncthreads();
            }
            if (t < H) __stcg(&g_kink2[m * H + t], th2s[t]);
            if (t <= H) {
                float bf0 = bf[l * 2], bf1 = bf[l * 2 + 1];
                float4 b4 = red4[0], s4 = scan4[t];
                float4 ef = make_float4(b4.x + s4.x, b4.y + s4.y + bf0,
                                        b4.z + s4.z, b4.w + s4.w + bf1);
                __stcg(&g_EF[m * NSEG + t], ef);
            }
        }
        gridbar();

        // ================= P3: apply (warp-uniform m from perm, lvl2 search) =================
        {
            float* kk2 = X + XO_KK2;   // [m*128 + r]
            for (int idx = t; idx < NSEG * H; idx += NT)
                kk2[idx] = __ldcg(&g_kink2[idx]);
            __syncthreads();

            const int P = __ldcg(&g_ptotal);
            float kS = 0.f, cS = 0.f, kQ = 0.f, cQ = 0.f;
            int gw = b * 32 + wid, nw = NB * 32;

            for (int base = gw * 32; base < P; base += nw * 32) {
                unsigned pv  = __ldcg(&g_perm[base + lane]);
                unsigned pv0 = __shfl_sync(0xffffffffu, pv, 0);   // lane 0 valid (32-aligned)
                int m = (int)(pv0 >> 18);
                bool valid = (pv != INVALID);
                unsigned i = valid ? (pv & 0x3FFFFu) : 0u;

                float2 p = __ldcg(((const float2*)g_x) + i);
                float u  = uIdx ? p.y : p.x;
                float xo = uIdx ? p.x : p.y;

                const float* kr = kk2 + m * H;
                int r = 0;
#pragma unroll
                for (int s = 64; s >= 1; s >>= 1) { int nr = r + s; if (kr[nr - 1] < u) r = nr; }
                if (kr[H - 1] < u) r = H;

                float4 ef = __ldcg(&g_EF[m * NSEG + r]);
                float st0 = fmaf(ef.x, u, ef.y);
                float st1 = fmaf(ef.z, u, ef.w);
                float e2  = __expf(2.f * st0);
                float sv  = 1.f - 2.f * __fdividef(1.f, e2 + 1.f);   // tanh
                float y   = fmaf(__expf(sv), xo, st1);

                if (valid) {
                    float sld = (l == 0 ? 0.f : __ldcg(&g_sldj[i])) + sv;
                    if (!isLast) {
                        __stcg(&g_x[2 * i + oIdx], y);
                        __stcg(&g_sldj[i], sld);
                        { float yk = y - cS;  float tk = kS + yk; cS = (tk - kS) - yk; kS = tk; }
                        float yy = y * y;
                        { float yk = yy - cQ; float tk = kQ + yk; cQ = (tk - kQ) - yk; kQ = tk; }
                    } else {
                        float zu = __fdividef(1.f, 1.f + __expf(-u));
                        float zo = __fdividef(1.f, 1.f + __expf(-y));
                        sld += __logf(zu * (1.f - zu) + FLOW_EPS) + __logf(zo * (1.f - zo) + FLOW_EPS);
                        out[2 * i + uIdx] = zu;
                        out[2 * i + oIdx] = zo;
                        out[2 * BATCH + i] = sld;
                    }
                }
            }

            if (!isLast) {
                double s = (double)kS, q = (double)kQ;
                for (int off = 16; off; off >>= 1) {
                    s += __shfl_down_sync(0xffffffffu, s, off);
                    q += __shfl_down_sync(0xffffffffu, q, off);
                }
                __shared__ double rs[32], rq[32];
                if (!lane) { rs[wid] = s; rq[wid] = q; }
                __syncthreads();
                if (!wid) {
                    s = (lane < NT / 32) ? rs[lane] : 0.0;
                    q = (lane < NT / 32) ? rq[lane] : 0.0;
                    for (int off = 16; off; off >>= 1) {
                        s += __shfl_down_sync(0xffffffffu, s, off);
                        q += __shfl_down_sync(0xffffffffu, q, off);
                    }
                    if (!lane) { atomicAdd(&g_sum[nxt][0], s); atomicAdd(&g_sum[nxt][1], q); }
                }
            }
        }
        if (!isLast) gridbar();
    }
}

// ---------------- host launcher ----------------
extern "C" void kernel_launch(void* const* d_in, const int* in_sizes, int n_in,
                              void* d_out, int out_size)
{
    const float* x    = (const float*)d_in[0];
    const float* v1   = (const float*)d_in[1];
    const float* g1   = (const float*)d_in[2];
    const float* b1   = (const float*)d_in[3];
    const float* bn1g = (const float*)d_in[4];
    const float* bn1b = (const float*)d_in[5];
    const float* v2   = (const float*)d_in[6];
    const float* g2   = (const float*)d_in[7];
    const float* b2   = (const float*)d_in[8];
    const float* bn2g = (const float*)d_in[9];
    const float* bn2b = (const float*)d_in[10];
    const float* wf   = (const float*)d_in[11];
    const float* bf   = (const float*)d_in[12];
    float* out = (float*)d_out;

    cudaFuncSetAttribute(k_all, cudaFuncAttributeMaxDynamicSharedMemorySize, SMEM_ALL);
    k_all<<<NB, NT, SMEM_ALL>>>(x, v1, g1, b1, bn1g, bn1b, v2, g2, b2,
                                bn2g, bn2b, wf, bf, out);
    (void)in_sizes; (void)n_in; (void)out_size;
}

// round 10
// speedup vs baseline: 1.2690x; 1.2690x over previous
#include <cuda_runtime.h>
#include <math_constants.h>

#define BATCH 262144
#define NLAYER 8
#define H 128
#define NSEG 129
#define BN_EPS 1e-5f
#define FLOW_EPS 1e-4f
#define INVALID 0xFFFFFFFFu
#define NREP 4
#define NB 148
#define NT 1024

// ---------------- device scratch (no allocs allowed) ----------------
__device__ unsigned g_arrive = 0, g_release = 0;   // grid barrier (monotonic, replay-safe)
__device__ double g_sum[2][2];                     // [parity][s,q]
__device__ int    g_cntR[2][NREP][NSEG];
__device__ float  g_s1R[2][NREP][NSEG], g_s2R[2][NREP][NSEG];
__device__ __align__(16) float g_tab[NSEG * H * 2];   // level-1 table (A,B per m,j)
__device__ __align__(8) float2 g_ghbh[H];             // BN2 fold factors
__device__ int    g_cursor[2][NSEG];
__device__ int    g_ptotal;
__device__ unsigned g_perm[BATCH + NSEG * 32];
__device__ unsigned char g_mseg[BATCH];
__device__ float g_x[2 * BATCH];
__device__ float g_sldj[BATCH];

// grid-wide barrier: all NB blocks resident by construction
__device__ __forceinline__ void gridbar()
{
    __syncthreads();
    if (threadIdx.x == 0) {
        unsigned old = *(volatile unsigned*)&g_release;
        __threadfence();
        if (atomicAdd(&g_arrive, 1) == NB - 1) {
            atomicExch(&g_arrive, 0);
            __threadfence();
            atomicExch(&g_release, old + 1);
        } else {
            while (*(volatile unsigned*)&g_release == old) __nanosleep(32);
        }
        __threadfence();
    }
    __syncthreads();
}

// shared layout (float offsets) in the X region after the float4 table area
#define XO_SA    0
#define XO_SC    128
#define XO_STHR  256
#define XO_STHS  384
#define XO_SORD  512
#define XO_SVR   640
#define XO_SCNT  768        // int[129]
#define XO_SS1   900        // hist floats / P3 bcnt ints
#define XO_SS2   1032       // hist floats / P3 bbase ints
#define XO_EOFF  1164       // int[130]
#define XO_GHBH  1296       // float[256]
#define XO_WS    1552       // warp partials (48)
#define XO_MISC  1600       // 8
#define X_FLOATS 1608
#define SMEM_ALL ((NSEG * 64 + 64) * 16 + X_FLOATS * 4)

__global__ void __launch_bounds__(NT, 1) k_all(
    const float* __restrict__ x,
    const float* __restrict__ v1,  const float* __restrict__ g1,  const float* __restrict__ b1,
    const float* __restrict__ bn1g,const float* __restrict__ bn1b,
    const float* __restrict__ v2,  const float* __restrict__ g2,  const float* __restrict__ b2,
    const float* __restrict__ bn2g,const float* __restrict__ bn2b,
    const float* __restrict__ wf,  const float* __restrict__ bf,
    float* __restrict__ out)
{
    extern __shared__ float sm[];
    float4* stab4 = (float4*)sm;                 // NSEG*64 float4 table
    float4* wf4   = stab4 + NSEG * 64;           // 64 float4
    float*  X     = (float*)(wf4 + 64);

    const int t = threadIdx.x, b = blockIdx.x;
    const int lane = t & 31, wid = t >> 5;

    // ================= P0: copy x, stats of x[:,1] into g_sum[0] =================
    {
        float kS = 0.f, cS = 0.f, kQ = 0.f, cQ = 0.f;
        for (int i = b * NT + t; i < BATCH; i += NB * NT) {
            float2 p = ((const float2*)x)[i];
            __stcg(((float2*)g_x) + i, p);
            float v = p.y;
            { float yk = v - cS; float tk = kS + yk; cS = (tk - kS) - yk; kS = tk; }
            float v2s = v * v;
            { float yk = v2s - cQ; float tk = kQ + yk; cQ = (tk - kQ) - yk; kQ = tk; }
        }
        double s = (double)kS, q = (double)kQ;
        for (int off = 16; off; off >>= 1) {
            s += __shfl_down_sync(0xffffffffu, s, off);
            q += __shfl_down_sync(0xffffffffu, q, off);
        }
        __shared__ double ss[32], sq[32];
        if (!lane) { ss[wid] = s; sq[wid] = q; }
        __syncthreads();
        if (!wid) {
            s = (lane < NT / 32) ? ss[lane] : 0.0;
            q = (lane < NT / 32) ? sq[lane] : 0.0;
            for (int off = 16; off; off >>= 1) {
                s += __shfl_down_sync(0xffffffffu, s, off);
                q += __shfl_down_sync(0xffffffffu, q, off);
            }
            if (!lane) { atomicAdd(&g_sum[0][0], s); atomicAdd(&g_sum[0][1], q); }
        }
        if (b == 1) {   // parity-0 buffers zero at start of each replay (idempotent)
            for (int idx = t; idx < NREP * NSEG; idx += NT) {
                ((int*)g_cntR[0])[idx] = 0;
                ((float*)g_s1R[0])[idx] = 0.f;
                ((float*)g_s2R[0])[idx] = 0.f;
            }
            for (int idx = t; idx < NSEG; idx += NT) g_cursor[0][idx] = 0;
        }
    }
    gridbar();

    for (int l = 0; l < NLAYER; l++) {
        const int par = l & 1, nxt = par ^ 1;
        const int uIdx = (l & 1) ^ 1, oIdx = 1 - uIdx;
        const int isLast = (l == NLAYER - 1);

        float* sa = X + XO_SA; float* sc = X + XO_SC; float* sthr = X + XO_STHR;
        float* sths = X + XO_STHS; int* sord = (int*)(X + XO_SORD); float* svr = X + XO_SVR;
        int* scnt = (int*)(X + XO_SCNT); float* ss1 = X + XO_SS1; float* ss2 = X + XO_SS2;
        float* WS = X + XO_WS; float* miscf = X + XO_MISC;

        // ================= P1: BN1 fold + lvl1 sort + lvl1 table build + hist =================
        if (t < H) {
            double mu = __ldcg(&g_sum[par][0]) * (1.0 / BATCH);
            double qq = __ldcg(&g_sum[par][1]) * (1.0 / BATCH);
            double var = qq - mu * mu;
            float meanu = (float)mu;
            float varu = (float)(var < 0.0 ? 0.0 : var);
            float v  = v1[l * H + t];
            float w1 = g1[l * H + t] * (v / fabsf(v));
            float r  = rsqrtf(w1 * w1 * varu + BN_EPS);
            float a  = w1 * bn1g[l * H + t] * r;
            float c  = bn1b[l * H + t] - a * meanu;
            sa[t] = a; sc[t] = c;
            sthr[t] = (a != 0.f) ? (-c / a) : CUDART_INF_F;
        }
        __syncthreads();
        if (t < H) {
            float th = sthr[t];
            int rank = 0;
            for (int j2 = 0; j2 < H; j2++) {
                float tj = sthr[j2];
                rank += (tj < th) || (tj == th && j2 < t);
            }
            sths[rank] = th; sord[rank] = t;
        }
        if (b == NB - 1) {  // zero next-parity buffers + next g_sum + next cursors
            for (int idx = t; idx < NREP * NSEG; idx += NT) {
                ((int*)g_cntR[nxt])[idx] = 0;
                ((float*)g_s1R[nxt])[idx] = 0.f;
                ((float*)g_s2R[nxt])[idx] = 0.f;
            }
            for (int idx = t; idx < NSEG; idx += NT) g_cursor[nxt][idx] = 0;
            if (t == 0) { g_sum[nxt][0] = 0.0; g_sum[nxt][1] = 0.0; }
        }
        __syncthreads();

        if (b < H) {  // build level-1 column j=b: register shfl reduce + scan
            const int j = b;
            if (t < H) svr[t] = v2[l * H * H + j * H + t];
            __syncthreads();
            // ||v2_j||^2 via warp reduce
            float nv = (t < H) ? svr[t] * svr[t] : 0.f;
#pragma unroll
            for (int o = 16; o; o >>= 1) nv += __shfl_xor_sync(0xffffffffu, nv, o);
            if (lane == 0 && wid < 8) WS[wid] = nv;
            __syncthreads();
            if (t == 0) miscf[0] = g2[l * H + j] / sqrtf(WS[0] + WS[1] + WS[2] + WS[3]);
            __syncthreads();
            float wsc = miscf[0];

            // base terms (u -> -inf) + scan deltas in registers
            float bA = 0.f, bB = 0.f;
            if (t < H) {
                float aa = sa[t], cc = sc[t], w = wsc * svr[t];
                if (aa < 0.f)                     { bA = w * aa; bB = w * cc; }
                else if (aa == 0.f && cc > 0.f)   { bB = w * cc; }
            }
            float dA = 0.f, dB = 0.f;
            if (t >= 1 && t <= H) {
                int kk = sord[t - 1];
                float aa = sa[kk], cc = sc[kk], w = wsc * svr[kk];
                float sgn = (aa > 0.f) ? 1.f : ((aa < 0.f) ? -1.f : 0.f);
                dA = sgn * w * aa; dB = sgn * w * cc;
            }
            // warp reduce base
            float rA = bA, rB = bB;
#pragma unroll
            for (int o = 16; o; o >>= 1) {
                rA += __shfl_xor_sync(0xffffffffu, rA, o);
                rB += __shfl_xor_sync(0xffffffffu, rB, o);
            }
            if (lane == 0 && wid < 8) { WS[0 + wid] = rA; WS[8 + wid] = rB; }
            // warp inclusive scan of deltas
            float sA = dA, sB = dB;
#pragma unroll
            for (int o = 1; o < 32; o <<= 1) {
                float uA = __shfl_up_sync(0xffffffffu, sA, o);
                float uB = __shfl_up_sync(0xffffffffu, sB, o);
                if (lane >= o) { sA += uA; sB += uB; }
            }
            if (lane == 31 && wid < 8) { WS[16 + wid] = sA; WS[24 + wid] = sB; }
            __syncthreads();
            if (t == 0) {
                miscf[1] = WS[0] + WS[1] + WS[2] + WS[3];                 // A0 (warps 0..3 cover t<128)
                miscf[2] = WS[8] + WS[9] + WS[10] + WS[11] + b2[l * H + j]; // B0
                float accA = 0.f, accB = 0.f;
#pragma unroll
                for (int w2 = 0; w2 < 5; w2++) {   // t<=128 lives in warps 0..4
                    WS[32 + w2] = accA; WS[40 + w2] = accB;
                    accA += WS[16 + w2]; accB += WS[24 + w2];
                }
            }
            __syncthreads();
            if (t <= H) {
                float2 val = make_float2(miscf[1] + WS[32 + wid] + sA,
                                         miscf[2] + WS[40 + wid] + sB);
                __stcg(((float2*)g_tab) + t * H + j, val);
            }
        }
        __syncthreads();

        // hist
        for (int i = t; i < NSEG; i += NT) { scnt[i] = 0; ss1[i] = 0.f; ss2[i] = 0.f; }
        __syncthreads();
        for (int i = b * NT + t; i < BATCH; i += NB * NT) {
            float2 p = __ldcg(((const float2*)g_x) + i);
            float u = uIdx ? p.y : p.x;
            int m = 0;
#pragma unroll
            for (int s = 64; s >= 1; s >>= 1) { int nm = m + s; if (sths[nm - 1] < u) m = nm; }
            if (sths[H - 1] < u) m = H;   // 7-step count saturates at 127
            __stcg(&g_mseg[i], (unsigned char)m);

            bool lo = (m == 0), hi = (m == H);
            float u2 = u * u;
            float s1l = lo ? u : 0.f, s2l = lo ? u2 : 0.f;
            float s1h = hi ? u : 0.f, s2h = hi ? u2 : 0.f;
#pragma unroll
            for (int off = 16; off; off >>= 1) {
                s1l += __shfl_xor_sync(0xffffffffu, s1l, off);
                s2l += __shfl_xor_sync(0xffffffffu, s2l, off);
                s1h += __shfl_xor_sync(0xffffffffu, s1h, off);
                s2h += __shfl_xor_sync(0xffffffffu, s2h, off);
            }
            unsigned blo = __ballot_sync(0xffffffffu, lo);
            unsigned bhi = __ballot_sync(0xffffffffu, hi);
            if (lane == 0) {
                if (blo) { atomicAdd(&scnt[0], (int)__popc(blo)); atomicAdd(&ss1[0], s1l); atomicAdd(&ss2[0], s2l); }
                if (bhi) { atomicAdd(&scnt[H], (int)__popc(bhi)); atomicAdd(&ss1[H], s1h); atomicAdd(&ss2[H], s2h); }
            }
            if (!lo && !hi) {
                atomicAdd(&scnt[m], 1);
                atomicAdd(&ss1[m], u);
                atomicAdd(&ss2[m], u2);
            }
        }
        __syncthreads();
        {
            int r = b & (NREP - 1);
            for (int i = t; i < NSEG; i += NT) {
                if (scnt[i]) {
                    atomicAdd(&g_cntR[par][r][i], scnt[i]);
                    atomicAdd(&g_s1R[par][r][i], ss1[i]);
                    atomicAdd(&g_s2R[par][r][i], ss2[i]);
                }
            }
        }
        gridbar();

        // ================= P3: offsets + scatter + ghbh (hidden behind scatter) ============
        {
            int* ecnt = (int*)(X + XO_SCNT);
            int* eoff = (int*)(X + XO_EOFF);
            int* bcnt = (int*)(X + XO_SS1);
            int* bbase = (int*)(X + XO_SS2);
            if (t < NSEG) {
                int c = 0;
#pragma unroll
                for (int r = 0; r < NREP; r++) c += __ldcg(&g_cntR[par][r][t]);
                ecnt[t] = c;
            }
            for (int i = t; i < NSEG; i += NT) bcnt[i] = 0;
            __syncthreads();
            if (t == 0) {
                int run = 0;
                for (int s = 0; s < NSEG; s++) { eoff[s] = run; run += (ecnt[s] + 31) & ~31; }
                eoff[NSEG] = run;
                if (b == 0) g_ptotal = run;
            }
            __syncthreads();
            int m0s = 0, m1s = 0, r0s = 0, r1s = 0, i0 = 0, i1 = 0;
            if (b < H) {
                i0 = b * 2048 + t; i1 = i0 + 1024;
                m0s = __ldcg(&g_mseg[i0]);
                m1s = __ldcg(&g_mseg[i1]);
                r0s = atomicAdd(&bcnt[m0s], 1);
                r1s = atomicAdd(&bcnt[m1s], 1);
            }
            __syncthreads();
            if (b < H && t < NSEG)
                bbase[t] = bcnt[t] ? atomicAdd(&g_cursor[par][t], bcnt[t]) : 0;
            __syncthreads();
            if (b < H) {
                __stcg(&g_perm[eoff[m0s] + bbase[m0s] + r0s], ((unsigned)m0s << 18) | (unsigned)i0);
                __stcg(&g_perm[eoff[m1s] + bbase[m1s] + r1s], ((unsigned)m1s << 18) | (unsigned)i1);
            }
            if (b < NSEG) {
                for (int p = eoff[b] + ecnt[b] + t; p < eoff[b + 1]; p += NT)
                    __stcg(&g_perm[p], INVALID);
            }
            // ghbh[j=b]: one term per thread (segment m=t), shfl reduce
            if (b < H) {
                const int j = b;
                float t1 = 0.f, t2 = 0.f;
                if (t < NSEG) {
                    float S1 = 0.f, S2 = 0.f;
#pragma unroll
                    for (int r = 0; r < NREP; r++) {
                        S1 += __ldcg(&g_s1R[par][r][t]);
                        S2 += __ldcg(&g_s2R[par][r][t]);
                    }
                    float N = (float)ecnt[t];
                    float2 ab = __ldcg(((const float2*)g_tab) + t * H + j);
                    t1 = ab.x * S1 + ab.y * N;
                    t2 = ab.x * (ab.x * S2 + 2.f * ab.y * S1) + ab.y * ab.y * N;
                }
#pragma unroll
                for (int o = 16; o; o >>= 1) {
                    t1 += __shfl_xor_sync(0xffffffffu, t1, o);
                    t2 += __shfl_xor_sync(0xffffffffu, t2, o);
                }
                if (lane == 0 && wid < 8) { WS[0 + wid] = t1; WS[8 + wid] = t2; }
                __syncthreads();
                if (t == 0) {
                    float m1 = WS[0] + WS[1] + WS[2] + WS[3] + WS[4];   // t<129 lives in warps 0..4
                    float m2 = WS[8] + WS[9] + WS[10] + WS[11] + WS[12];
                    float mean = m1 * (1.f / BATCH);
                    float var  = m2 * (1.f / BATCH) - mean * mean;
                    if (var < 0.f) var = 0.f;
                    float gh = bn2g[l * H + j] * rsqrtf(var + BN_EPS);
                    float bh = bn2b[l * H + j] - gh * mean;
                    __stcg(&g_ghbh[j], make_float2(gh, bh));
                }
            }
        }
        gridbar();

        // ================= P4: fused table load+fold, then apply (warp-uniform m) =========
        {
            float* ghbhS = X + XO_GHBH;
            if (t < 2 * H) ghbhS[t] = __ldcg(((const float*)g_ghbh) + t);
            for (int jj = t; jj < 64; jj += NT) {
                int j0 = 2 * jj, j1 = 2 * jj + 1;
                wf4[jj] = make_float4(wf[(l * 2 + 0) * H + j0], wf[(l * 2 + 1) * H + j0],
                                      wf[(l * 2 + 0) * H + j1], wf[(l * 2 + 1) * H + j1]);
            }
            __syncthreads();
            for (int idx = t; idx < NSEG * 64; idx += NT) {
                float4 tv = __ldcg(((const float4*)g_tab) + idx);
                int jp = (idx & 63) * 2;
                float g0 = ghbhS[2 * jp], b0 = ghbhS[2 * jp + 1];
                float g1v = ghbhS[2 * jp + 2], b1v = ghbhS[2 * jp + 3];
                stab4[idx] = make_float4(g0 * tv.x, fmaf(g0, tv.y, b0),
                                         g1v * tv.z, fmaf(g1v, tv.w, b1v));
            }
            __syncthreads();

            const int P = __ldcg(&g_ptotal);
            float bf0 = bf[l * 2], bf1 = bf[l * 2 + 1];
            float kS = 0.f, cS = 0.f, kQ = 0.f, cQ = 0.f;
            int gw = b * 32 + wid, nw = NB * 32;

            for (int base = gw * 32; base < P; base += nw * 32) {
                unsigned pv  = __ldcg(&g_perm[base + lane]);
                unsigned pv0 = __shfl_sync(0xffffffffu, pv, 0);   // lane 0 valid (32-aligned)
                int m0 = (int)(pv0 >> 18);
                bool valid = (pv != INVALID);
                unsigned i = valid ? (pv & 0x3FFFFu) : 0u;

                float2 p = __ldcg(((const float2*)g_x) + i);
                float u  = uIdx ? p.y : p.x;
                float xo = uIdx ? p.x : p.y;

                const float4* row = stab4 + m0 * 64;
                float st0a = 0.f, st1a = 0.f, st0b = 0.f, st1b = 0.f;
#pragma unroll 8
                for (int c = 0; c < 64; c += 2) {
                    float4 tv = row[c];     float4 w4 = wf4[c];
                    float h0 = fmaxf(fmaf(tv.x, u, tv.y), 0.f);
                    float h1 = fmaxf(fmaf(tv.z, u, tv.w), 0.f);
                    st0a = fmaf(w4.x, h0, fmaf(w4.z, h1, st0a));
                    st1a = fmaf(w4.y, h0, fmaf(w4.w, h1, st1a));
                    float4 tv2 = row[c + 1]; float4 w42 = wf4[c + 1];
                    float h2 = fmaxf(fmaf(tv2.x, u, tv2.y), 0.f);
                    float h3 = fmaxf(fmaf(tv2.z, u, tv2.w), 0.f);
                    st0b = fmaf(w42.x, h2, fmaf(w42.z, h3, st0b));
                    st1b = fmaf(w42.y, h2, fmaf(w42.w, h3, st1b));
                }
                float st0 = st0a + st0b + bf0;
                float st1 = st1a + st1b + bf1;
                float e2  = __expf(2.f * st0);
                float sv  = 1.f - 2.f * __fdividef(1.f, e2 + 1.f);   // tanh
                float y   = fmaf(__expf(sv), xo, st1);

                if (valid) {
                    float sld = (l == 0 ? 0.f : __ldcg(&g_sldj[i])) + sv;
                    if (!isLast) {
                        __stcg(&g_x[2 * i + oIdx], y);
                        __stcg(&g_sldj[i], sld);
                        { float yk = y - cS;  float tk = kS + yk; cS = (tk - kS) - yk; kS = tk; }
                        float yy = y * y;
                        { float yk = yy - cQ; float tk = kQ + yk; cQ = (tk - kQ) - yk; kQ = tk; }
                    } else {
                        float zu = __fdividef(1.f, 1.f + __expf(-u));
                        float zo = __fdividef(1.f, 1.f + __expf(-y));
                        sld += __logf(zu * (1.f - zu) + FLOW_EPS) + __logf(zo * (1.f - zo) + FLOW_EPS);
                        out[2 * i + uIdx] = zu;
                        out[2 * i + oIdx] = zo;
                        out[2 * BATCH + i] = sld;
                    }
                }
            }

            if (!isLast) {
                double s = (double)kS, q = (double)kQ;
                for (int off = 16; off; off >>= 1) {
                    s += __shfl_down_sync(0xffffffffu, s, off);
                    q += __shfl_down_sync(0xffffffffu, q, off);
                }
                __shared__ double rs[32], rq[32];
                if (!lane) { rs[wid] = s; rq[wid] = q; }
                __syncthreads();
                if (!wid) {
                    s = (lane < NT / 32) ? rs[lane] : 0.0;
                    q = (lane < NT / 32) ? rq[lane] : 0.0;
                    for (int off = 16; off; off >>= 1) {
                        s += __shfl_down_sync(0xffffffffu, s, off);
                        q += __shfl_down_sync(0xffffffffu, q, off);
                    }
                    if (!lane) { atomicAdd(&g_sum[nxt][0], s); atomicAdd(&g_sum[nxt][1], q); }
                }
            }
        }
        if (!isLast) gridbar();
    }
}

// ---------------- host launcher ----------------
extern "C" void kernel_launch(void* const* d_in, const int* in_sizes, int n_in,
                              void* d_out, int out_size)
{
    const float* x    = (const float*)d_in[0];
    const float* v1   = (const float*)d_in[1];
    const float* g1   = (const float*)d_in[2];
    const float* b1   = (const float*)d_in[3];
    const float* bn1g = (const float*)d_in[4];
    const float* bn1b = (const float*)d_in[5];
    const float* v2   = (const float*)d_in[6];
    const float* g2   = (const float*)d_in[7];
    const float* b2   = (const float*)d_in[8];
    const float* bn2g = (const float*)d_in[9];
    const float* bn2b = (const float*)d_in[10];
    const float* wf   = (const float*)d_in[11];
    const float* bf   = (const float*)d_in[12];
    float* out = (float*)d_out;

    cudaFuncSetAttribute(k_all, cudaFuncAttributeMaxDynamicSharedMemorySize, SMEM_ALL);
    k_all<<<NB, NT, SMEM_ALL>>>(x, v1, g1, b1, bn1g, bn1b, v2, g2, b2,
                                bn2g, bn2b, wf, bf, out);
    (void)in_sizes; (void)n_in; (void)out_size;
}